// round 1
// baseline (speedup 1.0000x reference)
#include <cuda_runtime.h>
#include <math.h>
#include <stdint.h>

#define B_ROWS 8192
#define D_DIM  1024
#define NTHREADS_SCAN 1024

// ---------------- scratch (static device globals; no runtime allocation) ----
__device__ int   g_M;
__device__ int   g_sel[B_ROWS];
__device__ int   g_lab[B_ROWS];
__device__ float g_fsel[(size_t)B_ROWS * D_DIM];           // 32 MB
__device__ float g_sim[(size_t)B_ROWS * (size_t)B_ROWS];   // 256 MB worst case
__device__ float g_rowloss[B_ROWS];

// ---------------- kernel 0: select + compaction (1 block, 1024 threads) -----
__global__ void __launch_bounds__(NTHREADS_SCAN)
k_select(const float* __restrict__ score, const void* __restrict__ labels_raw,
         const int* __restrict__ type_idx_p)
{
    const int t = threadIdx.x;
    __shared__ int s_is64;
    if (t == 0) {
        // detect labels dtype width: int64 little-endian -> odd 32-bit words are 0
        const int* L32 = (const int*)labels_raw;
        int z = 1;
        for (int k = 1; k < 128; k += 2) if (L32[k] != 0) { z = 0; break; }
        s_is64 = z;
    }
    __syncthreads();
    const int is64 = s_is64;
    const int ti = type_idx_p[0];   // low 32 bits correct for int32 or int64

    int flags[8];
    int lab8[8];
    int loc = 0;
#pragma unroll
    for (int q = 0; q < 8; q++) {
        int i = t * 8 + q;
        float s0 = score[3 * i + 0];
        float s1 = score[3 * i + 1];
        float s2 = score[3 * i + 2];
        int am = 0; float b = s0;
        if (s1 > b) { b = s1; am = 1; }
        if (s2 > b) { b = s2; am = 2; }
        flags[q] = (am == ti) ? 1 : 0;
        if (is64) lab8[q] = (int)(((const long long*)labels_raw)[i]);
        else      lab8[q] = ((const int*)labels_raw)[i];
        loc += flags[q];
    }

    __shared__ int sc[NTHREADS_SCAN];
    sc[t] = loc;
    __syncthreads();
    for (int off = 1; off < NTHREADS_SCAN; off <<= 1) {
        int v = (t >= off) ? sc[t - off] : 0;
        __syncthreads();
        sc[t] += v;
        __syncthreads();
    }
    int incl = sc[t];
    int pos = incl - loc;     // exclusive prefix
#pragma unroll
    for (int q = 0; q < 8; q++) {
        int i = t * 8 + q;
        if (flags[q]) {
            g_sel[pos] = i;
            g_lab[pos] = lab8[q];
            pos++;
        }
    }
    if (t == NTHREADS_SCAN - 1) g_M = incl;
}

// ---------------- kernel 1: gather + L2 normalize ---------------------------
__global__ void __launch_bounds__(256)
k_normalize(const float* __restrict__ feats)
{
    const int j = blockIdx.x;
    const int M = g_M;
    if (j >= M) return;
    const int src = g_sel[j];
    const int t = threadIdx.x;

    const float4 a = ((const float4*)(feats + (size_t)src * D_DIM))[t];
    float ss = a.x * a.x + a.y * a.y + a.z * a.z + a.w * a.w;

    __shared__ float red[256];
    red[t] = ss;
    __syncthreads();
    for (int off = 128; off > 0; off >>= 1) {
        if (t < off) red[t] += red[t + off];
        __syncthreads();
    }
    const float den = fmaxf(sqrtf(red[0]), 1e-12f);

    float4 o;
    o.x = a.x / den; o.y = a.y / den; o.z = a.z / den; o.w = a.w / den;
    ((float4*)(g_fsel + (size_t)j * D_DIM))[t] = o;
}

// ---------------- kernel 2: sim = fsel * fsel^T (fp32 SIMT GEMM) ------------
#define BM 128
#define BN 128
#define BK 16
#define TM 8
#define TN 8

__global__ void __launch_bounds__(256)
k_gemm()
{
    const int M = g_M;
    const int rt = blockIdx.y * BM;
    const int ct = blockIdx.x * BN;
    if (rt >= M || ct >= M) return;

    __shared__ float As[BK][BM];
    __shared__ float Bs[BK][BN];

    const int tid = threadIdx.x;
    const int ty = tid / 16;   // 0..15
    const int tx = tid % 16;   // 0..15

    float acc[TM][TN];
#pragma unroll
    for (int i = 0; i < TM; i++)
#pragma unroll
        for (int j = 0; j < TN; j++) acc[i][j] = 0.0f;

    const float* __restrict__ F = g_fsel;

    for (int k0 = 0; k0 < D_DIM; k0 += BK) {
#pragma unroll
        for (int u = 0; u < 2; u++) {
            const int f   = tid * 2 + u;   // 0..511
            const int row = f >> 2;        // 0..127
            const int c4  = f & 3;         // 0..3

            float4 va = make_float4(0.f, 0.f, 0.f, 0.f);
            const int gr = rt + row;
            if (gr < M) va = *(const float4*)(F + (size_t)gr * D_DIM + k0 + c4 * 4);
            As[c4 * 4 + 0][row] = va.x;
            As[c4 * 4 + 1][row] = va.y;
            As[c4 * 4 + 2][row] = va.z;
            As[c4 * 4 + 3][row] = va.w;

            float4 vb = make_float4(0.f, 0.f, 0.f, 0.f);
            const int gc = ct + row;
            if (gc < M) vb = *(const float4*)(F + (size_t)gc * D_DIM + k0 + c4 * 4);
            Bs[c4 * 4 + 0][row] = vb.x;
            Bs[c4 * 4 + 1][row] = vb.y;
            Bs[c4 * 4 + 2][row] = vb.z;
            Bs[c4 * 4 + 3][row] = vb.w;
        }
        __syncthreads();

#pragma unroll
        for (int kk = 0; kk < BK; kk++) {
            float ra[TM], rb[TN];
#pragma unroll
            for (int i = 0; i < TM; i++) ra[i] = As[kk][ty * TM + i];
#pragma unroll
            for (int j = 0; j < TN; j++) rb[j] = Bs[kk][tx * TN + j];
#pragma unroll
            for (int i = 0; i < TM; i++)
#pragma unroll
                for (int j = 0; j < TN; j++) acc[i][j] += ra[i] * rb[j];
        }
        __syncthreads();
    }

#pragma unroll
    for (int i = 0; i < TM; i++) {
        const int gr = rt + ty * TM + i;
        if (gr >= M) continue;
        float* dst = g_sim + (size_t)gr * (size_t)M;
#pragma unroll
        for (int j = 0; j < TN; j++) {
            const int gc = ct + tx * TN + j;
            if (gc < M) dst[gc] = acc[i][j];
        }
    }
}

// ---------------- kernel 3: per-row two-pass epilogue -----------------------
__global__ void __launch_bounds__(256)
k_rowloss()
{
    const int r = blockIdx.x;
    const int M = g_M;
    if (r >= M) return;
    const int t = threadIdx.x;
    const int labr = g_lab[r];
    const float* __restrict__ row = g_sim + (size_t)r * (size_t)M;
    const float INF = __int_as_float(0x7f800000);

    // pass 1: count, min_pos, max_neg
    float minpos = INF;
    float maxneg = -INF;
    int cnt = 0;
    for (int j = t; j < M; j += 256) {
        const int labj = g_lab[j];
        const float s = (j == r) ? 1.0f : row[j];
        const bool eq = (labj == labr);
        cnt += eq ? 1 : 0;
        if (eq && s < 1.0f - 1e-5f) minpos = fminf(minpos, s);
        if (!eq) maxneg = fmaxf(maxneg, s);
    }

    __shared__ float smin[256];
    __shared__ float smax[256];
    __shared__ int   scnt[256];
    smin[t] = minpos; smax[t] = maxneg; scnt[t] = cnt;
    __syncthreads();
    for (int off = 128; off > 0; off >>= 1) {
        if (t < off) {
            smin[t] = fminf(smin[t], smin[t + off]);
            smax[t] = fmaxf(smax[t], smax[t + off]);
            scnt[t] += scnt[t + off];
        }
        __syncthreads();
    }
    const float mp = smin[0];
    const float mn = smax[0];
    const int   c  = scnt[0];
    __syncthreads();

    // pass 2: hard-pair sums + any flags
    float psum = 0.f, nsum = 0.f;
    int anyp = 0, anyn = 0;
    for (int j = t; j < M; j += 256) {
        const int labj = g_lab[j];
        const float s = (j == r) ? 1.0f : row[j];
        const bool eq = (labj == labr);
        const bool pos0 = eq && (s < 1.0f - 1e-5f);
        const bool neg0 = !eq;
        if (neg0 && (s + 0.1f > mp)) { nsum += expf(40.0f * (s - 0.5f)); anyn = 1; }
        if (pos0 && (s - 0.1f < mn)) { psum += expf(-2.0f * (s - 0.5f)); anyp = 1; }
    }

    __shared__ float sp[256];
    __shared__ float sn[256];
    __shared__ int   sap[256];
    __shared__ int   san[256];
    sp[t] = psum; sn[t] = nsum; sap[t] = anyp; san[t] = anyn;
    __syncthreads();
    for (int off = 128; off > 0; off >>= 1) {
        if (t < off) {
            sp[t] += sp[t + off];
            sn[t] += sn[t + off];
            sap[t] |= sap[t + off];
            san[t] |= san[t + off];
        }
        __syncthreads();
    }
    if (t == 0) {
        const bool valid = (c > 1) && (mp < INF) && (mn > -INF) && sap[0] && san[0];
        g_rowloss[r] = valid ? (log1pf(sp[0]) / 2.0f + log1pf(sn[0]) / 40.0f) : 0.0f;
    }
}

// ---------------- kernel 4: deterministic final sum -------------------------
__global__ void __launch_bounds__(256)
k_finalize(float* __restrict__ out)
{
    const int M = g_M;
    const int t = threadIdx.x;
    float acc = 0.f;
    for (int i = t; i < M; i += 256) acc += g_rowloss[i];
    __shared__ float red[256];
    red[t] = acc;
    __syncthreads();
    for (int off = 128; off > 0; off >>= 1) {
        if (t < off) red[t] += red[t + off];
        __syncthreads();
    }
    if (t == 0) out[0] = red[0] / (float)B_ROWS;
}

// ---------------- launcher ---------------------------------------------------
extern "C" void kernel_launch(void* const* d_in, const int* in_sizes, int n_in,
                              void* d_out, int out_size)
{
    const float* feats  = (const float*)d_in[0];
    const void*  labels = d_in[1];
    const float* score  = (const float*)d_in[2];
    const int*   tidx   = (const int*)d_in[3];
    float* out = (float*)d_out;

    k_select<<<1, NTHREADS_SCAN>>>(score, labels, tidx);
    k_normalize<<<B_ROWS, 256>>>(feats);
    dim3 grid(B_ROWS / BN, B_ROWS / BM);
    k_gemm<<<grid, 256>>>();
    k_rowloss<<<B_ROWS, 256>>>();
    k_finalize<<<1, 256>>>(out);
}

// round 3
// speedup vs baseline: 3.7016x; 3.7016x over previous
#include <cuda_runtime.h>
#include <cuda_bf16.h>
#include <math.h>
#include <stdint.h>

#define B_ROWS 8192
#define D_DIM  1024
#define NTHREADS_SCAN 1024

// ---------------- scratch (static device globals) ---------------------------
__device__ int   g_M;
__device__ int   g_sel[B_ROWS];
__device__ int   g_lab[B_ROWS];
__device__ __align__(128) __nv_bfloat16 g_hi[(size_t)B_ROWS * D_DIM];   // 16 MB
__device__ __align__(128) __nv_bfloat16 g_lo[(size_t)B_ROWS * D_DIM];   // 16 MB
__device__ __align__(128) float g_sim[(size_t)B_ROWS * (size_t)B_ROWS];
__device__ float g_rowloss[B_ROWS];

__device__ __forceinline__ uint32_t smem_u32(const void* p) {
    uint32_t a;
    asm("{ .reg .u64 t; cvta.to.shared.u64 t, %1; cvt.u32.u64 %0, t; }" : "=r"(a) : "l"(p));
    return a;
}

// ---------------- kernel 0: select + compaction ------------------------------
__global__ void __launch_bounds__(NTHREADS_SCAN)
k_select(const float* __restrict__ score, const void* __restrict__ labels_raw,
         const int* __restrict__ type_idx_p)
{
    const int t = threadIdx.x;
    __shared__ int s_is64;
    if (t == 0) {
        const int* L32 = (const int*)labels_raw;
        int z = 1;
        for (int k = 1; k < 128; k += 2) if (L32[k] != 0) { z = 0; break; }
        s_is64 = z;
    }
    __syncthreads();
    const int is64 = s_is64;
    const int ti = type_idx_p[0];

    int flags[8], lab8[8], loc = 0;
#pragma unroll
    for (int q = 0; q < 8; q++) {
        int i = t * 8 + q;
        float s0 = score[3 * i + 0], s1 = score[3 * i + 1], s2 = score[3 * i + 2];
        int am = 0; float b = s0;
        if (s1 > b) { b = s1; am = 1; }
        if (s2 > b) { b = s2; am = 2; }
        flags[q] = (am == ti) ? 1 : 0;
        if (is64) lab8[q] = (int)(((const long long*)labels_raw)[i]);
        else      lab8[q] = ((const int*)labels_raw)[i];
        loc += flags[q];
    }

    __shared__ int sc[NTHREADS_SCAN];
    sc[t] = loc;
    __syncthreads();
    for (int off = 1; off < NTHREADS_SCAN; off <<= 1) {
        int v = (t >= off) ? sc[t - off] : 0;
        __syncthreads();
        sc[t] += v;
        __syncthreads();
    }
    int incl = sc[t];
    int pos = incl - loc;
#pragma unroll
    for (int q = 0; q < 8; q++) {
        int i = t * 8 + q;
        if (flags[q]) { g_sel[pos] = i; g_lab[pos] = lab8[q]; pos++; }
    }
    if (t == NTHREADS_SCAN - 1) g_M = incl;
}

// ---------------- kernel 1: gather + L2 normalize + bf16 hi/lo split ---------
__global__ void __launch_bounds__(256)
k_normalize(const float* __restrict__ feats)
{
    const int j = blockIdx.x;
    const int M = g_M;
    const int Mpad = (M + 127) & ~127;
    if (j >= Mpad) return;
    const int t = threadIdx.x;

    if (j >= M) {   // zero pad rows
        ((uint2*)(g_hi + (size_t)j * D_DIM))[t] = make_uint2(0, 0);
        ((uint2*)(g_lo + (size_t)j * D_DIM))[t] = make_uint2(0, 0);
        return;
    }
    const int src = g_sel[j];
    const float4 a = ((const float4*)(feats + (size_t)src * D_DIM))[t];
    float ss = a.x * a.x + a.y * a.y + a.z * a.z + a.w * a.w;

    __shared__ float red[256];
    red[t] = ss;
    __syncthreads();
    for (int off = 128; off > 0; off >>= 1) {
        if (t < off) red[t] += red[t + off];
        __syncthreads();
    }
    const float inv = 1.0f / fmaxf(sqrtf(red[0]), 1e-12f);

    float o[4] = { a.x * inv, a.y * inv, a.z * inv, a.w * inv };
    __nv_bfloat16 h[4], l[4];
#pragma unroll
    for (int q = 0; q < 4; q++) {
        h[q] = __float2bfloat16_rn(o[q]);
        l[q] = __float2bfloat16_rn(o[q] - __bfloat162float(h[q]));
    }
    uint2 hp, lp;
    hp.x = (uint32_t)(*(uint16_t*)&h[0]) | ((uint32_t)(*(uint16_t*)&h[1]) << 16);
    hp.y = (uint32_t)(*(uint16_t*)&h[2]) | ((uint32_t)(*(uint16_t*)&h[3]) << 16);
    lp.x = (uint32_t)(*(uint16_t*)&l[0]) | ((uint32_t)(*(uint16_t*)&l[1]) << 16);
    lp.y = (uint32_t)(*(uint16_t*)&l[2]) | ((uint32_t)(*(uint16_t*)&l[3]) << 16);
    ((uint2*)(g_hi + (size_t)j * D_DIM))[t] = hp;
    ((uint2*)(g_lo + (size_t)j * D_DIM))[t] = lp;
}

// ---------------- kernel 2: mma.sync bf16 hi/lo GEMM (symmetric tiles) -------
#define TILE 128
#define KC 64
#define NCHUNK (D_DIM / KC)                   // 16
#define TILE_BYTES (TILE * 128)               // 16384
#define STAGE_BYTES (4 * TILE_BYTES)          // 65536
#define GEMM_SMEM (2 * STAGE_BYTES)           // 131072

__device__ __forceinline__ void ldsm4(uint32_t* r, uint32_t addr) {
    asm volatile("ldmatrix.sync.aligned.m8n8.x4.shared.b16 {%0,%1,%2,%3}, [%4];"
                 : "=r"(r[0]), "=r"(r[1]), "=r"(r[2]), "=r"(r[3]) : "r"(addr));
}
__device__ __forceinline__ void mma16816(float* d, const uint32_t* a, const uint32_t* b) {
    asm volatile(
        "mma.sync.aligned.m16n8k16.row.col.f32.bf16.bf16.f32 "
        "{%0,%1,%2,%3}, {%4,%5,%6,%7}, {%8,%9}, {%0,%1,%2,%3};"
        : "+f"(d[0]), "+f"(d[1]), "+f"(d[2]), "+f"(d[3])
        : "r"(a[0]), "r"(a[1]), "r"(a[2]), "r"(a[3]), "r"(b[0]), "r"(b[1]));
}

__global__ void __launch_bounds__(256, 1)
k_gemm()
{
    const int M = g_M;
    const int tiles = (M + 127) >> 7;
    const int bx = blockIdx.x, by = blockIdx.y;
    if (by >= tiles || bx > by) return;        // lower-triangle tiles only
    const int ldm = tiles << 7;
    const int rt = by * TILE;
    const int ct = bx * TILE;
    const int tid = threadIdx.x;
    const int lane = tid & 31;
    const int wid = tid >> 5;
    const int wm = wid >> 1;                   // 0..3  (32-row slice)
    const int wn = wid & 1;                    // 0..1  (64-col slice)

    extern __shared__ __align__(1024) char smc[];
    const uint32_t tb = smem_u32(smc);

    // ---- chunk loader: 4 tiles (Ahi, Alo, Bhi, Blo), 16 B cp.async each ----
    auto load_chunk = [&](int kc, int stage) {
        const uint32_t sb = tb + stage * STAGE_BYTES;
        const int kb = kc * KC;
#pragma unroll
        for (int i = 0; i < 16; i++) {
            const int c = tid + i * 256;       // 0..4095
            const int tix = c >> 10;           // 0..3
            const int r   = (c >> 3) & 127;
            const int seg = c & 7;
            const __nv_bfloat16* base = (tix & 1) ? g_lo : g_hi;
            const int rowbase = (tix < 2) ? rt : ct;
            const __nv_bfloat16* src = base + (size_t)(rowbase + r) * D_DIM + kb + seg * 8;
            uint32_t dst = sb + tix * TILE_BYTES + r * 128 + ((seg ^ (r & 7)) << 4);
            asm volatile("cp.async.cg.shared.global [%0], [%1], 16;" :: "r"(dst), "l"(src));
        }
        asm volatile("cp.async.commit_group;");
    };

    float acc[2][8][4];
#pragma unroll
    for (int mf = 0; mf < 2; mf++)
#pragma unroll
        for (int nf = 0; nf < 8; nf++)
#pragma unroll
            for (int i = 0; i < 4; i++) acc[mf][nf][i] = 0.0f;

    load_chunk(0, 0);
    load_chunk(1, 1);

    for (int k = 0; k < NCHUNK; k++) {
        if (k == NCHUNK - 1) asm volatile("cp.async.wait_group 0;" ::: "memory");
        else                 asm volatile("cp.async.wait_group 1;" ::: "memory");
        __syncthreads();

        const uint32_t sb  = tb + (k & 1) * STAGE_BYTES;
        const uint32_t Ahi = sb;
        const uint32_t Alo = sb + TILE_BYTES;
        const uint32_t Bhi = sb + 2 * TILE_BYTES;
        const uint32_t Blo = sb + 3 * TILE_BYTES;

#pragma unroll
        for (int ks = 0; ks < 4; ks++) {
            uint32_t ah[2][4], al[2][4];
#pragma unroll
            for (int mf = 0; mf < 2; mf++) {
                const int row = wm * 32 + mf * 16 + (lane & 15);
                const int seg = ks * 2 + (lane >> 4);
                const uint32_t off = row * 128 + ((seg ^ (row & 7)) << 4);
                ldsm4(ah[mf], Ahi + off);
                ldsm4(al[mf], Alo + off);
            }
            uint32_t bh[4][4], bl[4][4];
#pragma unroll
            for (int nq = 0; nq < 4; nq++) {
                const int row = wn * 64 + nq * 16 + (lane & 7) + ((lane >> 4) << 3);
                const int seg = ks * 2 + ((lane >> 3) & 1);
                const uint32_t off = row * 128 + ((seg ^ (row & 7)) << 4);
                ldsm4(bh[nq], Bhi + off);
                ldsm4(bl[nq], Blo + off);
            }
#pragma unroll
            for (int mf = 0; mf < 2; mf++)
#pragma unroll
                for (int nf = 0; nf < 8; nf++) {
                    const uint32_t* bhp = &bh[nf >> 1][(nf & 1) * 2];
                    const uint32_t* blp = &bl[nf >> 1][(nf & 1) * 2];
                    mma16816(acc[mf][nf], ah[mf], bhp);   // hi*hi
                    mma16816(acc[mf][nf], ah[mf], blp);   // hi*lo
                    mma16816(acc[mf][nf], al[mf], bhp);   // lo*hi
                }
        }
        __syncthreads();
        if (k + 2 < NCHUNK) load_chunk(k + 2, k & 1);
    }

    // ---- epilogue: direct stores (this tile) ----
#pragma unroll
    for (int mf = 0; mf < 2; mf++)
#pragma unroll
        for (int nf = 0; nf < 8; nf++) {
            const int r0 = rt + wm * 32 + mf * 16 + (lane >> 2);
            const int c0 = ct + wn * 64 + nf * 8 + (lane & 3) * 2;
            *(float2*)(g_sim + (size_t)r0 * ldm + c0)       = make_float2(acc[mf][nf][0], acc[mf][nf][1]);
            *(float2*)(g_sim + (size_t)(r0 + 8) * ldm + c0) = make_float2(acc[mf][nf][2], acc[mf][nf][3]);
        }

    // ---- mirror (transpose via SMEM) for off-diagonal tiles ----
    if (bx != by) {
        float* S = (float*)smc;      // [128][136]
#pragma unroll
        for (int mf = 0; mf < 2; mf++)
#pragma unroll
            for (int nf = 0; nf < 8; nf++) {
                const int rl = wm * 32 + mf * 16 + (lane >> 2);
                const int cl = wn * 64 + nf * 8 + (lane & 3) * 2;
                S[cl * 136 + rl]           = acc[mf][nf][0];
                S[(cl + 1) * 136 + rl]     = acc[mf][nf][1];
                S[cl * 136 + rl + 8]       = acc[mf][nf][2];
                S[(cl + 1) * 136 + rl + 8] = acc[mf][nf][3];
            }
        __syncthreads();
        for (int i = tid; i < 128 * 32; i += 256) {
            const int row = i >> 5;            // transposed row (orig col)
            const int c4  = (i & 31) * 4;
            float4 v = make_float4(S[row * 136 + c4], S[row * 136 + c4 + 1],
                                   S[row * 136 + c4 + 2], S[row * 136 + c4 + 3]);
            *(float4*)(g_sim + (size_t)(ct + row) * ldm + rt + c4) = v;
        }
    }
}

// ---------------- kernel 3: per-row epilogue ---------------------------------
__global__ void __launch_bounds__(256)
k_rowloss()
{
    const int r = blockIdx.x;
    const int M = g_M;
    if (r >= M) return;
    const int Mpad = (M + 127) & ~127;
    const int t = threadIdx.x;

    __shared__ int slab[B_ROWS];
    for (int j = t; j < M; j += 256) slab[j] = g_lab[j];
    __syncthreads();

    const int labr = slab[r];
    const float* __restrict__ row = g_sim + (size_t)r * (size_t)Mpad;
    const float INF = __int_as_float(0x7f800000);

    float sv[32];
    unsigned eqm = 0u;
    float minpos = INF, maxneg = -INF;
    int cnt = 0;
#pragma unroll
    for (int u = 0; u < 32; u++) {
        const int j = t + u * 256;
        if (j < M) {
            const float s = (j == r) ? 1.0f : row[j];
            sv[u] = s;
            const bool eq = (slab[j] == labr);
            if (eq) { eqm |= (1u << u); cnt++; if (s < 1.0f - 1e-5f) minpos = fminf(minpos, s); }
            else maxneg = fmaxf(maxneg, s);
        } else sv[u] = 0.0f;
    }

    __shared__ float smin[256], smax[256];
    __shared__ int scnt[256];
    smin[t] = minpos; smax[t] = maxneg; scnt[t] = cnt;
    __syncthreads();
    for (int off = 128; off > 0; off >>= 1) {
        if (t < off) {
            smin[t] = fminf(smin[t], smin[t + off]);
            smax[t] = fmaxf(smax[t], smax[t + off]);
            scnt[t] += scnt[t + off];
        }
        __syncthreads();
    }
    const float mp = smin[0];
    const float mn = smax[0];
    const int   c  = scnt[0];
    __syncthreads();

    float psum = 0.f, nsum = 0.f;
    int anyp = 0, anyn = 0;
#pragma unroll
    for (int u = 0; u < 32; u++) {
        const int j = t + u * 256;
        if (j >= M) break;
        const float s = sv[u];
        const bool eq = (eqm >> u) & 1u;
        if (!eq) {
            if (s + 0.1f > mp) { nsum += expf(40.0f * (s - 0.5f)); anyn = 1; }
        } else if (s < 1.0f - 1e-5f && s - 0.1f < mn) {
            psum += expf(-2.0f * (s - 0.5f)); anyp = 1;
        }
    }

    __shared__ float sp[256], sn[256];
    __shared__ int sap[256], san[256];
    sp[t] = psum; sn[t] = nsum; sap[t] = anyp; san[t] = anyn;
    __syncthreads();
    for (int off = 128; off > 0; off >>= 1) {
        if (t < off) {
            sp[t] += sp[t + off];
            sn[t] += sn[t + off];
            sap[t] |= sap[t + off];
            san[t] |= san[t + off];
        }
        __syncthreads();
    }
    if (t == 0) {
        const bool valid = (c > 1) && (mp < INF) && (mn > -INF) && sap[0] && san[0];
        g_rowloss[r] = valid ? (log1pf(sp[0]) / 2.0f + log1pf(sn[0]) / 40.0f) : 0.0f;
    }
}

// ---------------- kernel 4: deterministic final sum --------------------------
__global__ void __launch_bounds__(256)
k_finalize(float* __restrict__ out)
{
    const int M = g_M;
    const int t = threadIdx.x;
    float acc = 0.f;
    for (int i = t; i < M; i += 256) acc += g_rowloss[i];
    __shared__ float red[256];
    red[t] = acc;
    __syncthreads();
    for (int off = 128; off > 0; off >>= 1) {
        if (t < off) red[t] += red[t + off];
        __syncthreads();
    }
    if (t == 0) out[0] = red[0] / (float)B_ROWS;
}

// ---------------- launcher ---------------------------------------------------
extern "C" void kernel_launch(void* const* d_in, const int* in_sizes, int n_in,
                              void* d_out, int out_size)
{
    const float* feats  = (const float*)d_in[0];
    const void*  labels = d_in[1];
    const float* score  = (const float*)d_in[2];
    const int*   tidx   = (const int*)d_in[3];
    float* out = (float*)d_out;

    cudaFuncSetAttribute(k_gemm, cudaFuncAttributeMaxDynamicSharedMemorySize, GEMM_SMEM);

    k_select<<<1, NTHREADS_SCAN>>>(score, labels, tidx);
    k_normalize<<<B_ROWS, 256>>>(feats);
    dim3 grid(B_ROWS / TILE, B_ROWS / TILE);
    k_gemm<<<grid, 256, GEMM_SMEM>>>();
    k_rowloss<<<B_ROWS, 256>>>();
    k_finalize<<<1, 256>>>(out);
}

// round 4
// speedup vs baseline: 4.6024x; 1.2434x over previous
#include <cuda_runtime.h>
#include <cuda_bf16.h>
#include <math.h>
#include <stdint.h>

#define B_ROWS 8192
#define D_DIM  1024
#define NTHREADS_SCAN 1024

// ---------------- scratch (static device globals) ---------------------------
__device__ int   g_M;
__device__ int   g_sel[B_ROWS];
__device__ int   g_lab[B_ROWS];
__device__ __align__(128) __nv_bfloat16 g_hi[(size_t)B_ROWS * D_DIM];   // 16 MB
__device__ __align__(128) __nv_bfloat16 g_lo[(size_t)B_ROWS * D_DIM];   // 16 MB
__device__ __align__(128) float g_sim[(size_t)B_ROWS * (size_t)B_ROWS];
__device__ float g_rowloss[B_ROWS];

__device__ __forceinline__ uint32_t smem_u32(const void* p) {
    uint32_t a;
    asm("{ .reg .u64 t; cvta.to.shared.u64 t, %1; cvt.u32.u64 %0, t; }" : "=r"(a) : "l"(p));
    return a;
}

// ---------------- kernel 0: select + compaction ------------------------------
__global__ void __launch_bounds__(NTHREADS_SCAN)
k_select(const float* __restrict__ score, const void* __restrict__ labels_raw,
         const int* __restrict__ type_idx_p)
{
    const int t = threadIdx.x;
    __shared__ int s_is64;
    if (t == 0) {
        const int* L32 = (const int*)labels_raw;
        int z = 1;
        for (int k = 1; k < 128; k += 2) if (L32[k] != 0) { z = 0; break; }
        s_is64 = z;
    }
    __syncthreads();
    const int is64 = s_is64;
    const int ti = type_idx_p[0];

    int flags[8], lab8[8], loc = 0;
#pragma unroll
    for (int q = 0; q < 8; q++) {
        int i = t * 8 + q;
        float s0 = score[3 * i + 0], s1 = score[3 * i + 1], s2 = score[3 * i + 2];
        int am = 0; float b = s0;
        if (s1 > b) { b = s1; am = 1; }
        if (s2 > b) { b = s2; am = 2; }
        flags[q] = (am == ti) ? 1 : 0;
        if (is64) lab8[q] = (int)(((const long long*)labels_raw)[i]);
        else      lab8[q] = ((const int*)labels_raw)[i];
        loc += flags[q];
    }

    __shared__ int sc[NTHREADS_SCAN];
    sc[t] = loc;
    __syncthreads();
    for (int off = 1; off < NTHREADS_SCAN; off <<= 1) {
        int v = (t >= off) ? sc[t - off] : 0;
        __syncthreads();
        sc[t] += v;
        __syncthreads();
    }
    int incl = sc[t];
    int pos = incl - loc;
#pragma unroll
    for (int q = 0; q < 8; q++) {
        int i = t * 8 + q;
        if (flags[q]) { g_sel[pos] = i; g_lab[pos] = lab8[q]; pos++; }
    }
    if (t == NTHREADS_SCAN - 1) g_M = incl;
}

// ---------------- kernel 1: gather + L2 normalize + bf16 hi/lo split ---------
__global__ void __launch_bounds__(256)
k_normalize(const float* __restrict__ feats)
{
    const int j = blockIdx.x;
    const int M = g_M;
    const int Mpad = (M + 127) & ~127;
    if (j >= Mpad) return;
    const int t = threadIdx.x;

    if (j >= M) {   // zero pad rows
        ((uint2*)(g_hi + (size_t)j * D_DIM))[t] = make_uint2(0, 0);
        ((uint2*)(g_lo + (size_t)j * D_DIM))[t] = make_uint2(0, 0);
        return;
    }
    const int src = g_sel[j];
    const float4 a = ((const float4*)(feats + (size_t)src * D_DIM))[t];
    float ss = a.x * a.x + a.y * a.y + a.z * a.z + a.w * a.w;

    __shared__ float red[256];
    red[t] = ss;
    __syncthreads();
    for (int off = 128; off > 0; off >>= 1) {
        if (t < off) red[t] += red[t + off];
        __syncthreads();
    }
    const float inv = 1.0f / fmaxf(sqrtf(red[0]), 1e-12f);

    float o[4] = { a.x * inv, a.y * inv, a.z * inv, a.w * inv };
    __nv_bfloat16 h[4], l[4];
#pragma unroll
    for (int q = 0; q < 4; q++) {
        h[q] = __float2bfloat16_rn(o[q]);
        l[q] = __float2bfloat16_rn(o[q] - __bfloat162float(h[q]));
    }
    uint2 hp, lp;
    hp.x = (uint32_t)(*(uint16_t*)&h[0]) | ((uint32_t)(*(uint16_t*)&h[1]) << 16);
    hp.y = (uint32_t)(*(uint16_t*)&h[2]) | ((uint32_t)(*(uint16_t*)&h[3]) << 16);
    lp.x = (uint32_t)(*(uint16_t*)&l[0]) | ((uint32_t)(*(uint16_t*)&l[1]) << 16);
    lp.y = (uint32_t)(*(uint16_t*)&l[2]) | ((uint32_t)(*(uint16_t*)&l[3]) << 16);
    ((uint2*)(g_hi + (size_t)j * D_DIM))[t] = hp;
    ((uint2*)(g_lo + (size_t)j * D_DIM))[t] = lp;
}

// ---------------- kernel 2: mma.sync bf16 hi/lo GEMM (symmetric tiles) -------
#define TILE 128
#define KC 64
#define NCHUNK (D_DIM / KC)                   // 16
#define TILE_BYTES (TILE * 128)               // 16384
#define STAGE_BYTES (4 * TILE_BYTES)          // 65536
#define NSTAGE 3
#define GEMM_SMEM (NSTAGE * STAGE_BYTES)      // 196608

__device__ __forceinline__ void ldsm4(uint32_t* r, uint32_t addr) {
    asm volatile("ldmatrix.sync.aligned.m8n8.x4.shared.b16 {%0,%1,%2,%3}, [%4];"
                 : "=r"(r[0]), "=r"(r[1]), "=r"(r[2]), "=r"(r[3]) : "r"(addr));
}
__device__ __forceinline__ void mma16816(float* d, const uint32_t* a, const uint32_t* b) {
    asm volatile(
        "mma.sync.aligned.m16n8k16.row.col.f32.bf16.bf16.f32 "
        "{%0,%1,%2,%3}, {%4,%5,%6,%7}, {%8,%9}, {%0,%1,%2,%3};"
        : "+f"(d[0]), "+f"(d[1]), "+f"(d[2]), "+f"(d[3])
        : "r"(a[0]), "r"(a[1]), "r"(a[2]), "r"(a[3]), "r"(b[0]), "r"(b[1]));
}

__global__ void __launch_bounds__(256, 1)
k_gemm()
{
    const int M = g_M;
    const int tiles = (M + 127) >> 7;
    const int bx = blockIdx.x, by = blockIdx.y;
    if (by >= tiles || bx > by) return;        // lower-triangle tiles only
    const int ldm = tiles << 7;
    const int rt = by * TILE;
    const int ct = bx * TILE;
    const int tid = threadIdx.x;
    const int lane = tid & 31;
    const int wid = tid >> 5;
    const int wm = wid >> 1;                   // 0..3  (32-row slice)
    const int wn = wid & 1;                    // 0..1  (64-col slice)

    extern __shared__ __align__(1024) char smc[];
    const uint32_t tb = smem_u32(smc);

    // ---- chunk loader: 4 tiles (Ahi, Alo, Bhi, Blo), 16 B cp.async each ----
    auto load_chunk = [&](int kc, int stage) {
        const uint32_t sb = tb + stage * STAGE_BYTES;
        const int kb = kc * KC;
#pragma unroll
        for (int i = 0; i < 16; i++) {
            const int c = tid + i * 256;       // 0..4095
            const int tix = c >> 10;           // 0..3
            const int r   = (c >> 3) & 127;
            const int seg = c & 7;
            const __nv_bfloat16* base = (tix & 1) ? g_lo : g_hi;
            const int rowbase = (tix < 2) ? rt : ct;
            const __nv_bfloat16* src = base + (size_t)(rowbase + r) * D_DIM + kb + seg * 8;
            uint32_t dst = sb + tix * TILE_BYTES + r * 128 + ((seg ^ (r & 7)) << 4);
            asm volatile("cp.async.cg.shared.global [%0], [%1], 16;" :: "r"(dst), "l"(src));
        }
        asm volatile("cp.async.commit_group;");
    };

    float acc[2][8][4];
#pragma unroll
    for (int mf = 0; mf < 2; mf++)
#pragma unroll
        for (int nf = 0; nf < 8; nf++)
#pragma unroll
            for (int i = 0; i < 4; i++) acc[mf][nf][i] = 0.0f;

    load_chunk(0, 0);
    load_chunk(1, 1);
    load_chunk(2, 2);

    for (int k = 0; k < NCHUNK; k++) {
        if (k + 3 <= NCHUNK)      asm volatile("cp.async.wait_group 2;" ::: "memory");
        else if (k + 2 == NCHUNK) asm volatile("cp.async.wait_group 1;" ::: "memory");
        else                      asm volatile("cp.async.wait_group 0;" ::: "memory");
        __syncthreads();

        const int st = k % NSTAGE;
        const uint32_t sb  = tb + st * STAGE_BYTES;
        const uint32_t Ahi = sb;
        const uint32_t Alo = sb + TILE_BYTES;
        const uint32_t Bhi = sb + 2 * TILE_BYTES;
        const uint32_t Blo = sb + 3 * TILE_BYTES;

#pragma unroll
        for (int ks = 0; ks < 4; ks++) {
            uint32_t ah[2][4], al[2][4];
#pragma unroll
            for (int mf = 0; mf < 2; mf++) {
                const int row = wm * 32 + mf * 16 + (lane & 15);
                const int seg = ks * 2 + (lane >> 4);
                const uint32_t off = row * 128 + ((seg ^ (row & 7)) << 4);
                ldsm4(ah[mf], Ahi + off);
                ldsm4(al[mf], Alo + off);
            }
            uint32_t bh[4][4], bl[4][4];
#pragma unroll
            for (int nq = 0; nq < 4; nq++) {
                const int row = wn * 64 + nq * 16 + (lane & 7) + ((lane >> 4) << 3);
                const int seg = ks * 2 + ((lane >> 3) & 1);
                const uint32_t off = row * 128 + ((seg ^ (row & 7)) << 4);
                ldsm4(bh[nq], Bhi + off);
                ldsm4(bl[nq], Blo + off);
            }
#pragma unroll
            for (int mf = 0; mf < 2; mf++)
#pragma unroll
                for (int nf = 0; nf < 8; nf++) {
                    const uint32_t* bhp = &bh[nf >> 1][(nf & 1) * 2];
                    const uint32_t* blp = &bl[nf >> 1][(nf & 1) * 2];
                    mma16816(acc[mf][nf], ah[mf], bhp);   // hi*hi
                    mma16816(acc[mf][nf], ah[mf], blp);   // hi*lo
                    mma16816(acc[mf][nf], al[mf], bhp);   // lo*hi
                }
        }
        __syncthreads();
        if (k + 3 < NCHUNK) load_chunk(k + 3, st);
    }

    // ---- epilogue: direct stores (this tile) ----
#pragma unroll
    for (int mf = 0; mf < 2; mf++)
#pragma unroll
        for (int nf = 0; nf < 8; nf++) {
            const int r0 = rt + wm * 32 + mf * 16 + (lane >> 2);
            const int c0 = ct + wn * 64 + nf * 8 + (lane & 3) * 2;
            *(float2*)(g_sim + (size_t)r0 * ldm + c0)       = make_float2(acc[mf][nf][0], acc[mf][nf][1]);
            *(float2*)(g_sim + (size_t)(r0 + 8) * ldm + c0) = make_float2(acc[mf][nf][2], acc[mf][nf][3]);
        }

    // ---- mirror (transpose via SMEM) for off-diagonal tiles ----
    if (bx != by) {
        float* S = (float*)smc;      // [128][136]
#pragma unroll
        for (int mf = 0; mf < 2; mf++)
#pragma unroll
            for (int nf = 0; nf < 8; nf++) {
                const int rl = wm * 32 + mf * 16 + (lane >> 2);
                const int cl = wn * 64 + nf * 8 + (lane & 3) * 2;
                S[cl * 136 + rl]           = acc[mf][nf][0];
                S[(cl + 1) * 136 + rl]     = acc[mf][nf][1];
                S[cl * 136 + rl + 8]       = acc[mf][nf][2];
                S[(cl + 1) * 136 + rl + 8] = acc[mf][nf][3];
            }
        __syncthreads();
        for (int i = tid; i < 128 * 32; i += 256) {
            const int row = i >> 5;            // transposed row (orig col)
            const int c4  = (i & 31) * 4;
            float4 v = make_float4(S[row * 136 + c4], S[row * 136 + c4 + 1],
                                   S[row * 136 + c4 + 2], S[row * 136 + c4 + 3]);
            *(float4*)(g_sim + (size_t)(ct + row) * ldm + rt + c4) = v;
        }
    }
}

// ---------------- kernel 3: per-row epilogue (lean, 2 light passes) ----------
__global__ void __launch_bounds__(256)
k_rowloss()
{
    const int r = blockIdx.x;
    const int M = g_M;
    if (r >= M) return;
    const int Mpad = (M + 127) & ~127;
    const int t = threadIdx.x;
    const int lane = t & 31;
    const int w = t >> 5;
    const int labr = __ldg(&g_lab[r]);
    const float* __restrict__ row = g_sim + (size_t)r * (size_t)Mpad;
    const float INF = __int_as_float(0x7f800000);
    const float C1 = 1.0f - 1e-5f;

    // pass 1: count, min_pos, max_neg
    float minpos = INF, maxneg = -INF;
    int cnt = 0;
    for (int j = t; j < M; j += 256) {
        const float s = (j == r) ? 1.0f : __ldg(row + j);
        const bool eq = (__ldg(&g_lab[j]) == labr);
        if (eq) { cnt++; if (s < C1) minpos = fminf(minpos, s); }
        else maxneg = fmaxf(maxneg, s);
    }
#pragma unroll
    for (int o = 16; o; o >>= 1) {
        minpos = fminf(minpos, __shfl_xor_sync(0xffffffffu, minpos, o));
        maxneg = fmaxf(maxneg, __shfl_xor_sync(0xffffffffu, maxneg, o));
        cnt += __shfl_xor_sync(0xffffffffu, cnt, o);
    }
    __shared__ float w_min[8], w_max[8];
    __shared__ int w_cnt[8];
    if (lane == 0) { w_min[w] = minpos; w_max[w] = maxneg; w_cnt[w] = cnt; }
    __syncthreads();
    float mp = INF, mn = -INF;
    int c = 0;
#pragma unroll
    for (int q = 0; q < 8; q++) { mp = fminf(mp, w_min[q]); mn = fmaxf(mn, w_max[q]); c += w_cnt[q]; }

    // validity (any(neg_sel) <=> mn+MARGIN>mp ; any(pos_sel) <=> mp-MARGIN<mn : same cond)
    const bool valid = (c > 1) && (mp < INF) && (mn > -INF) && (mn > mp - 0.1f);
    if (!valid) {
        if (t == 0) g_rowloss[r] = 0.0f;
        return;
    }

    // pass 2: hard-pair sums
    float psum = 0.f, nsum = 0.f;
    for (int j = t; j < M; j += 256) {
        const float s = (j == r) ? 1.0f : __ldg(row + j);
        const bool eq = (__ldg(&g_lab[j]) == labr);
        if (!eq) {
            if (s + 0.1f > mp) nsum += __expf(40.0f * (s - 0.5f));
        } else if (s < C1 && s - 0.1f < mn) {
            psum += __expf(-2.0f * (s - 0.5f));
        }
    }
#pragma unroll
    for (int o = 16; o; o >>= 1) {
        psum += __shfl_xor_sync(0xffffffffu, psum, o);
        nsum += __shfl_xor_sync(0xffffffffu, nsum, o);
    }
    __shared__ float w_p[8], w_n[8];
    if (lane == 0) { w_p[w] = psum; w_n[w] = nsum; }
    __syncthreads();
    if (t == 0) {
        float P = 0.f, N = 0.f;
#pragma unroll
        for (int q = 0; q < 8; q++) { P += w_p[q]; N += w_n[q]; }
        g_rowloss[r] = log1pf(P) / 2.0f + log1pf(N) / 40.0f;
    }
}

// ---------------- kernel 4: deterministic final sum --------------------------
__global__ void __launch_bounds__(256)
k_finalize(float* __restrict__ out)
{
    const int M = g_M;
    const int t = threadIdx.x;
    float acc = 0.f;
    for (int i = t; i < M; i += 256) acc += g_rowloss[i];
    __shared__ float red[256];
    red[t] = acc;
    __syncthreads();
    for (int off = 128; off > 0; off >>= 1) {
        if (t < off) red[t] += red[t + off];
        __syncthreads();
    }
    if (t == 0) out[0] = red[0] / (float)B_ROWS;
}

// ---------------- launcher ---------------------------------------------------
extern "C" void kernel_launch(void* const* d_in, const int* in_sizes, int n_in,
                              void* d_out, int out_size)
{
    const float* feats  = (const float*)d_in[0];
    const void*  labels = d_in[1];
    const float* score  = (const float*)d_in[2];
    const int*   tidx   = (const int*)d_in[3];
    float* out = (float*)d_out;

    cudaFuncSetAttribute(k_gemm, cudaFuncAttributeMaxDynamicSharedMemorySize, GEMM_SMEM);

    k_select<<<1, NTHREADS_SCAN>>>(score, labels, tidx);
    k_normalize<<<B_ROWS, 256>>>(feats);
    dim3 grid(B_ROWS / TILE, B_ROWS / TILE);
    k_gemm<<<grid, 256, GEMM_SMEM>>>();
    k_rowloss<<<B_ROWS, 256>>>();
    k_finalize<<<1, 256>>>(out);
}